// round 10
// baseline (speedup 1.0000x reference)
#include <cuda_runtime.h>
#include <math.h>
#include <stdint.h>

#define MAXS 2048
#define HSIZE 8192
#define HMASK 8191
#define NBLK 148
#define NTHR 256
#define SMEMF 28800            // dynamic smem floats per block (112.5KB)
#define TILE_MIN 224

#define EPI_NONE 0
#define EPI_TANH 1
#define EPI_CADJ 2

typedef unsigned long long ull;

struct Params {
  const int *heads, *tails;
  const float *times;
  const float *node_rep, *cell_head, *hidden_head, *cell_tail, *hidden_tail;
  const float *Weh1, *Weh2, *beh, *Wet1, *Wet2, *bet;
  const float *Wxh, *Whh, *bh, *Wdh, *bdh;
  const float *Wxt, *Wht, *bt, *Wdt, *bdt;
  const float *Wc1, *Wc2;
  float *out;
  int S;
};

__device__ int g_cidH[MAXS], g_cidT[MAXS];
__device__ int g_slotNode[HSIZE];
__device__ int g_stepList[MAXS];
__device__ int g_waveOff[MAXS + 2];
__device__ int g_numWaves;

__device__ float c_rep[HSIZE * 128];
__device__ float c_ch [HSIZE * 128];
__device__ float c_hh [HSIZE * 128];
__device__ float c_ct [HSIZE * 128];
__device__ float c_ht [HSIZE * 128];
__device__ float c_rt [HSIZE];

__device__ unsigned g_barCnt;
__device__ volatile unsigned g_barGen;

__device__ __forceinline__ void grid_barrier() {
  __syncthreads();
  if (threadIdx.x == 0) {
    unsigned gen = g_barGen;
    __threadfence();
    if (atomicAdd(&g_barCnt, 1u) == gridDim.x - 1) {
      g_barCnt = 0; __threadfence(); g_barGen = gen + 1;
    } else {
      while (g_barGen == gen) { __nanosleep(32); }
    }
    __threadfence();
  }
  __syncthreads();
}

__device__ __forceinline__ float sigf(float x) { return 1.0f / (1.0f + expf(-x)); }
__device__ __forceinline__ void FFMA2(ull &d, ull a, ull b) {
  asm("fma.rn.f32x2 %0, %1, %2, %0;" : "+l"(d) : "l"(a), "l"(b));
}
__device__ __forceinline__ ull ADD2(ull a, ull b) {
  ull d; asm("add.rn.f32x2 %0, %1, %2;" : "=l"(d) : "l"(a), "l"(b)); return d;
}
__device__ __forceinline__ ull pack2(float a) {
  ull d; asm("mov.b64 %0, {%1, %1};" : "=l"(d) : "f"(a)); return d;
}
__device__ __forceinline__ void cpa16(uint32_t s, const float* g) {
  asm volatile("cp.async.cg.shared.global [%0], [%1], 16;" :: "r"(s), "l"(g));
}
#define CPA_COMMIT() asm volatile("cp.async.commit_group;")
#define CPA_WAIT1()  asm volatile("cp.async.wait_group 1;")
#define CPA_WAIT0()  asm volatile("cp.async.wait_group 0;")

// ============================ scheduler =====================================
__global__ void __launch_bounds__(1024) scheduler_kernel(const int* heads, const int* tails, int S) {
  __shared__ int buf[HSIZE];
  __shared__ unsigned short sCH[MAXS], sCT[MAXS];
  __shared__ unsigned char asg[MAXS];
  __shared__ int sCnt, sBase, sW, sRemain;
  const int tid = threadIdx.x;
  for (int i = tid; i < HSIZE; i += 1024) { buf[i] = 0; g_slotNode[i] = -1; }
  for (int s = tid; s < S; s += 1024) asg[s] = 0;
  if (tid == 0) { sBase = 0; sW = 0; sRemain = S; }
  __syncthreads();
  for (int i = tid; i < 2 * S; i += 1024) {
    int step = i >> 1, isT = i & 1;
    int node = isT ? tails[step] : heads[step];
    int key = node + 1;
    unsigned slot = ((unsigned)node * 2654435761u) & HMASK;
    while (true) {
      int cur = buf[slot];
      if (cur == key) break;
      if (cur == 0) {
        int old = atomicCAS(&buf[slot], 0, key);
        if (old == 0) { g_slotNode[slot] = node; break; }
        if (old == key) break;
      }
      slot = (slot + 1u) & HMASK;
    }
    if (isT) { sCT[step] = (unsigned short)slot; g_cidT[step] = (int)slot; }
    else     { sCH[step] = (unsigned short)slot; g_cidH[step] = (int)slot; }
  }
  __syncthreads();
  while (sRemain > 0) {
    for (int s = tid; s < S; s += 1024)
      if (!asg[s]) { buf[sCH[s]] = 0x7FFFFFFF; buf[sCT[s]] = 0x7FFFFFFF; }
    __syncthreads();
    for (int s = tid; s < S; s += 1024)
      if (!asg[s]) { atomicMin(&buf[sCH[s]], 2 * s); atomicMin(&buf[sCT[s]], 2 * s + 1); }
    if (tid == 0) sCnt = 0;
    __syncthreads();
    for (int s = tid; s < S; s += 1024)
      if (!asg[s]) {
        int ch = sCH[s], ct = sCT[s];
        if (buf[ch] == 2 * s && (ct == ch || buf[ct] == 2 * s + 1)) {
          asg[s] = 1;
          g_stepList[sBase + atomicAdd(&sCnt, 1)] = s;
        }
      }
    __syncthreads();
    if (tid == 0) {
      g_waveOff[sW] = sBase; sBase += sCnt; sRemain -= sCnt; sW += 1; g_waveOff[sW] = sBase;
    }
    __syncthreads();
  }
  if (tid == 0) g_numWaves = sW;
}

// ==================== tiled GEMM (16 rows x 128 cols) =======================
// out = epi(A1@W1 (+A2@W2) + bias). A in smem [16*128]. W streamed cp.async.
// k-split: warp w -> rows (w&3)*4..+3, k-sub (w>>2)*16 of each 32-chunk.
// Partials merged through an 8KB smem reduction before the epilogue.
// zpass>=0: column map col -> (col>>5)*128 + zpass*32 + (col&31) for W/bias.
struct GArgs {
  const float *A1, *A2, *W1, *W2, *bias, *CA, *dec;
  float *outS; float* const* outG; float* sW;
  int ldw, zpass, epi;
};
__device__ void gemmT(const GArgs& a) {
  const int tid = threadIdx.x;
  const int w = tid >> 5, l = tid & 31;
  const int rg = (w & 3) << 2;       // 4 rows per warp
  const int ks = (w >> 2) << 4;      // k-sub: 0 or 16
  const int nch = a.A2 ? 8 : 4;
  // stage chunk 0
  {
    const float* W = a.W1;
#pragma unroll
    for (int i = 0; i < 4; ++i) {
      int e = tid + i * NTHR, kk = e >> 5, c4 = (e & 31) << 2;
      int col = (a.zpass >= 0) ? ((c4 >> 5) * 128 + a.zpass * 32 + (c4 & 31)) : c4;
      cpa16((uint32_t)__cvta_generic_to_shared(a.sW + kk * 128 + c4),
            W + (size_t)kk * a.ldw + col);
    }
    CPA_COMMIT();
  }
  ull acc[4][2];
#pragma unroll
  for (int r = 0; r < 4; ++r) { acc[r][0] = 0; acc[r][1] = 0; }

  for (int c = 0; c < nch; ++c) {
    if (c + 1 < nch) {
      const float* W = (c + 1 >= 4) ? a.W2 : a.W1;
      int k0 = ((c + 1) & 3) * 32;
      float* Wb = a.sW + ((c + 1) & 1) * 4096;
#pragma unroll
      for (int i = 0; i < 4; ++i) {
        int e = tid + i * NTHR, kk = e >> 5, c4 = (e & 31) << 2;
        int col = (a.zpass >= 0) ? ((c4 >> 5) * 128 + a.zpass * 32 + (c4 & 31)) : c4;
        cpa16((uint32_t)__cvta_generic_to_shared(Wb + kk * 128 + c4),
              W + (size_t)(k0 + kk) * a.ldw + col);
      }
      CPA_COMMIT();
      CPA_WAIT1();
    } else {
      CPA_WAIT0();
    }
    __syncthreads();
    const float* A = (c >= 4) ? a.A2 : a.A1;
    const int k0 = (c & 3) * 32 + ks;
    const float* Wb = a.sW + (c & 1) * 4096 + ks * 128;
#pragma unroll
    for (int kg = 0; kg < 4; ++kg) {
      float ab[4][4];
#pragma unroll
      for (int r = 0; r < 4; ++r)
        *(float4*)ab[r] = *(const float4*)&A[(rg + r) * 128 + k0 + kg * 4];
#pragma unroll
      for (int kk = 0; kk < 4; ++kk) {
        ulonglong2 wv = *(const ulonglong2*)&Wb[(kg * 4 + kk) * 128 + (l << 2)];
#pragma unroll
        for (int r = 0; r < 4; ++r) {
          ull av = pack2(ab[r][kk]);
          FFMA2(acc[r][0], av, wv.x);
          FFMA2(acc[r][1], av, wv.y);
        }
      }
    }
    __syncthreads();
  }

  // k-split merge: warps 4-7 publish partials into sW (free after last chunk)
  ull* red = (ull*)a.sW;
  if (w >= 4) {
    ull* dst = red + (((w - 4) * 32 + l) << 3);
#pragma unroll
    for (int r = 0; r < 4; ++r) { dst[2 * r] = acc[r][0]; dst[2 * r + 1] = acc[r][1]; }
  }
  __syncthreads();
  if (w < 4) {
    const ull* src = red + ((w * 32 + l) << 3);
#pragma unroll
    for (int r = 0; r < 4; ++r) {
      acc[r][0] = ADD2(acc[r][0], src[2 * r]);
      acc[r][1] = ADD2(acc[r][1], src[2 * r + 1]);
    }
    union U { ull u; float2 f; };
#pragma unroll
    for (int r = 0; r < 4; ++r) {
      int row = rg + r;
      U u0, u1; u0.u = acc[r][0]; u1.u = acc[r][1];
      float vals[4] = {u0.f.x, u0.f.y, u1.f.x, u1.f.y};
      float* og = a.outG ? a.outG[row] : 0;
#pragma unroll
      for (int j = 0; j < 4; ++j) {
        int col = (l << 2) + j;
        float v = vals[j];
        if (a.bias) {
          int bc = (a.zpass >= 0) ? ((col >> 5) * 128 + a.zpass * 32 + (col & 31)) : col;
          v += a.bias[bc];
        }
        if (a.epi == EPI_TANH) v = tanhf(v);
        else if (a.epi == EPI_CADJ) {
          float cs = tanhf(v);
          v = a.CA[row * 128 + col] + cs * (a.dec[row] - 1.0f);
        }
        if (a.outS) a.outS[row * 128 + col] = v;
        else if (og) og[col] = v;
      }
    }
  }
  __syncthreads();
}

// ============================== main kernel =================================
__global__ void __launch_bounds__(NTHR) main_kernel(Params p) {
  extern __shared__ float sm[];
  float *X1 = sm, *X2 = sm + 2048, *E1 = sm + 4096, *E2 = sm + 6144;
  float *H1 = sm + 8192, *H2 = sm + 10240, *S1 = sm + 12288, *S2 = sm + 14336;
  float *Z = sm + 16384, *CA = sm + 18432, *WS = sm + 20480;
  int   *slotH = (int*)(sm + 28672), *slotT = slotH + 16, *valid = slotT + 16;
  float *decH = (float*)(valid + 16), *decT = decH + 16;
  float **og = (float**)(decT + 16);

  const int tid = threadIdx.x;
  const int gsize = gridDim.x * blockDim.x;
  const int gtid = blockIdx.x * blockDim.x + tid;
  const int S = p.S;

  // init gather
  for (int e = gtid; e < HSIZE * 32; e += gsize) {
    int slot = e >> 5, q = (e & 31) << 2;
    int node = g_slotNode[slot];
    if (node < 0) continue;
    size_t src = (size_t)node * 128 + q;
    size_t dst = (size_t)slot * 128 + q;
    *(float4*)&c_rep[dst] = *(const float4*)&p.node_rep[src];
    *(float4*)&c_ch[dst]  = *(const float4*)&p.cell_head[src];
    *(float4*)&c_hh[dst]  = *(const float4*)&p.hidden_head[src];
    *(float4*)&c_ct[dst]  = *(const float4*)&p.cell_tail[src];
    *(float4*)&c_ht[dst]  = *(const float4*)&p.hidden_tail[src];
    if (q == 0) c_rt[slot] = 0.0f;
  }
  grid_barrier();

  const int nW = g_numWaves;
  for (int w = 0; w < nW; ++w) {
    const int s0 = g_waveOff[w];
    const int M = g_waveOff[w + 1] - s0;

    if (M >= TILE_MIN) {
      // ================= tiled path: 16 steps per block-job =================
      const int mT = (M + 15) >> 4;
      for (int job = blockIdx.x; job < mT; job += gridDim.x) {
        int m0 = job * 16;
        if (tid < 16) {
          int m = m0 + tid;
          int v = (m < M);
          int step = g_stepList[s0 + (v ? m : (M - 1))];
          int ch = g_cidH[step], ct = g_cidT[step];
          slotH[tid] = ch; slotT[tid] = ct; valid[tid] = v;
          float tm = p.times[step];
          decH[tid] = expf(-(tm - c_rt[ch]));
          decT[tid] = expf(-(tm - c_rt[ct]));
          if (v) { c_rt[ch] = tm; c_rt[ct] = tm; }
        }
        __syncthreads();
        for (int e = tid; e < 512; e += NTHR) {
          int r = e >> 5, q = (e & 31) << 2;
          int ch = slotH[r], ct = slotT[r];
          float4 rh = *(const float4*)&c_rep[ch * 128 + q];
          float4 rt = *(const float4*)&c_rep[ct * 128 + q];
          *(float4*)&X1[r * 128 + q] = rh;
          *(float4*)&X2[r * 128 + q] = rt;
          *(float4*)&H1[r * 128 + q] = *(const float4*)&c_hh[ch * 128 + q];
          *(float4*)&H2[r * 128 + q] = *(const float4*)&c_ht[ct * 128 + q];
          *(float4*)&S1[r * 128 + q] = *(const float4*)&c_ht[ch * 128 + q];
          *(float4*)&S2[r * 128 + q] = *(const float4*)&c_hh[ct * 128 + q];
          if (valid[r]) {
            int step = g_stepList[s0 + m0 + r];
            *(float4*)&p.out[(size_t)step * 128 + q] = rh;
            *(float4*)&p.out[(size_t)(S + step) * 128 + q] = rt;
          }
        }
        __syncthreads();
        GArgs a; a.sW = WS; a.CA = 0; a.dec = 0; a.outG = 0; a.zpass = -1;
        a.A1 = X1; a.A2 = X2; a.W1 = p.Weh1; a.W2 = p.Weh2; a.ldw = 128;
        a.bias = p.beh; a.epi = EPI_TANH; a.outS = E1; gemmT(a);
        a.W1 = p.Wet1; a.W2 = p.Wet2; a.bias = p.bet; a.outS = E2; gemmT(a);
        for (int e = tid; e < 512; e += NTHR) {
          int r = e >> 5, q = (e & 31) << 2;
          *(float4*)&CA[r * 128 + q] = *(const float4*)&c_ch[slotH[r] * 128 + q];
        }
        __syncthreads();
        a.A1 = CA; a.A2 = 0; a.W1 = p.Wdh; a.W2 = 0; a.bias = p.bdh;
        a.epi = EPI_CADJ; a.CA = CA; a.dec = decH; a.outS = X1; gemmT(a);
        for (int e = tid; e < 512; e += NTHR) {
          int r = e >> 5, q = (e & 31) << 2;
          *(float4*)&CA[r * 128 + q] = *(const float4*)&c_ct[slotT[r] * 128 + q];
        }
        __syncthreads();
        a.W1 = p.Wdt; a.bias = p.bdt; a.dec = decT; a.outS = X2; gemmT(a);
        for (int side = 0; side < 2; ++side) {
          float* E = side ? E2 : E1;
          float* Hs = side ? H2 : H1;
          float* Xc = side ? X2 : X1;
          float* cel = side ? c_ct : c_ch;
          float* hid = side ? c_ht : c_hh;
          int* slot = side ? slotT : slotH;
          GArgs b; b.sW = WS; b.A1 = E; b.A2 = Hs;
          b.W1 = side ? p.Wxt : p.Wxh; b.W2 = side ? p.Wht : p.Whh;
          b.ldw = 512; b.bias = side ? p.bt : p.bh; b.epi = EPI_NONE;
          b.CA = 0; b.dec = 0; b.outS = Z; b.outG = 0;
          for (int pass = 0; pass < 4; ++pass) {
            b.zpass = pass; gemmT(b);
            for (int e = tid; e < 512; e += NTHR) {
              int r = e >> 5, c = e & 31;
              if (!valid[r]) continue;
              float ii = sigf(Z[r * 128 + c]);
              float ff = sigf(Z[r * 128 + 32 + c]);
              float oo = sigf(Z[r * 128 + 64 + c]);
              float gg = tanhf(Z[r * 128 + 96 + c]);
              int col = pass * 32 + c;
              float cn = ff * Xc[r * 128 + col] + ii * gg;
              float hn = oo * tanhf(cn);
              Xc[r * 128 + col] = hn;
              cel[slot[r] * 128 + col] = cn;
              hid[slot[r] * 128 + col] = hn;
            }
            __syncthreads();
          }
        }
        if (tid < 16)
          og[tid] = (valid[tid] && slotH[tid] != slotT[tid]) ? (c_rep + slotH[tid] * 128) : 0;
        __syncthreads();
        a.A1 = X1; a.A2 = S1; a.W1 = p.Wc1; a.W2 = p.Wc2; a.ldw = 128;
        a.bias = 0; a.epi = EPI_TANH; a.CA = 0; a.dec = 0;
        a.outS = 0; a.outG = og; gemmT(a);
        if (tid < 16) og[tid] = valid[tid] ? (c_rep + slotT[tid] * 128) : 0;
        __syncthreads();
        a.A1 = S2; a.A2 = X2; gemmT(a);
      }
    } else {
      // ================= GEMV path: one step per block-job ==================
      float *aRH = sm, *aRT = sm + 128, *aHH = sm + 256, *aHT = sm + 384;
      float *aTh = sm + 512, *aHt = sm + 640, *aCH = sm + 768, *aCT = sm + 896;
      float *eH = sm + 1024, *eT = sm + 1152, *cjH = sm + 1280, *cjT = sm + 1408;
      float *hnH = sm + 1536, *hnT = sm + 1664;
      float *zz = sm + 1792;
      float *dc = sm + 2816;
      for (int job = blockIdx.x; job < M; job += gridDim.x) {
        int step = g_stepList[s0 + job];
        int ch = g_cidH[step], ct = g_cidT[step];
        if (tid == 0) {
          float tm = p.times[step];
          dc[0] = expf(-(tm - c_rt[ch]));
          dc[1] = expf(-(tm - c_rt[ct]));
          c_rt[ch] = tm; c_rt[ct] = tm;
        }
        if (tid < 128) {
          int t = tid;
          float rh = c_rep[ch * 128 + t], rt = c_rep[ct * 128 + t];
          aRH[t] = rh; aRT[t] = rt;
          aHH[t] = c_hh[ch * 128 + t]; aHT[t] = c_ht[ct * 128 + t];
          aTh[t] = c_ht[ch * 128 + t]; aHt[t] = c_hh[ct * 128 + t];
          aCH[t] = c_ch[ch * 128 + t]; aCT[t] = c_ct[ct * 128 + t];
          p.out[(size_t)step * 128 + t] = rh;
          p.out[(size_t)(S + step) * 128 + t] = rt;
        }
        __syncthreads();
        if (tid < 64) {
          int side = tid >> 5, q = (tid & 31) << 2;
          const float *W1 = side ? p.Wet1 : p.Weh1, *W2 = side ? p.Wet2 : p.Weh2;
          const float *bb = side ? p.bet : p.beh;
          float4 acc = *(const float4*)&bb[q];
          for (int k = 0; k < 128; ++k) {
            float a0 = aRH[k], a1 = aRT[k];
            float4 w1 = *(const float4*)&W1[k * 128 + q];
            float4 w2 = *(const float4*)&W2[k * 128 + q];
            acc.x += a0 * w1.x + a1 * w2.x; acc.y += a0 * w1.y + a1 * w2.y;
            acc.z += a0 * w1.z + a1 * w2.z; acc.w += a0 * w1.w + a1 * w2.w;
          }
          float* e = side ? eT : eH;
          e[q] = tanhf(acc.x); e[q + 1] = tanhf(acc.y);
          e[q + 2] = tanhf(acc.z); e[q + 3] = tanhf(acc.w);
        } else if (tid < 128) {
          int side = (tid >> 5) & 1, q = (tid & 31) << 2;
          const float* Wd = side ? p.Wdt : p.Wdh;
          const float* bd = side ? p.bdt : p.bdh;
          const float* cc = side ? aCT : aCH;
          float d = dc[side];
          float4 acc = *(const float4*)&bd[q];
          for (int k = 0; k < 128; ++k) {
            float a0 = cc[k];
            float4 wv = *(const float4*)&Wd[k * 128 + q];
            acc.x += a0 * wv.x; acc.y += a0 * wv.y; acc.z += a0 * wv.z; acc.w += a0 * wv.w;
          }
          float* cj = side ? cjT : cjH;
          cj[q] = cc[q] + tanhf(acc.x) * (d - 1.f);
          cj[q + 1] = cc[q + 1] + tanhf(acc.y) * (d - 1.f);
          cj[q + 2] = cc[q + 2] + tanhf(acc.z) * (d - 1.f);
          cj[q + 3] = cc[q + 3] + tanhf(acc.w) * (d - 1.f);
        }
        __syncthreads();
        {
          int side = tid >> 7, gate = (tid >> 5) & 3, q = (tid & 31) << 2;
          int col = gate * 128 + q;
          const float* Wx = side ? p.Wxt : p.Wxh;
          const float* Wh = side ? p.Wht : p.Whh;
          const float* bb = side ? p.bt : p.bh;
          const float* e = side ? eT : eH;
          const float* hh = side ? aHT : aHH;
          float4 acc = *(const float4*)&bb[col];
          for (int k = 0; k < 128; ++k) {
            float x = e[k], h = hh[k];
            float4 w1 = *(const float4*)&Wx[k * 512 + col];
            float4 w2 = *(const float4*)&Wh[k * 512 + col];
            acc.x += x * w1.x + h * w2.x; acc.y += x * w1.y + h * w2.y;
            acc.z += x * w1.z + h * w2.z; acc.w += x * w1.w + h * w2.w;
          }
          *(float4*)&zz[side * 512 + col] = acc;
        }
        __syncthreads();
        {
          int side = tid >> 7, c = tid & 127;
          const float* z = zz + side * 512;
          float ii = sigf(z[c]), ff = sigf(z[128 + c]), oo = sigf(z[256 + c]), gg = tanhf(z[384 + c]);
          float cn = ff * (side ? cjT[c] : cjH[c]) + ii * gg;
          float hn = oo * tanhf(cn);
          if (side) { hnT[c] = hn; c_ct[ct * 128 + c] = cn; c_ht[ct * 128 + c] = hn; }
          else      { hnH[c] = hn; c_ch[ch * 128 + c] = cn; c_hh[ch * 128 + c] = hn; }
        }
        __syncthreads();
        if (tid < 64) {
          int side = tid >> 5, q = (tid & 31) << 2;
          const float* a1 = side ? aHt : hnH;
          const float* a2 = side ? hnT : aTh;
          float4 acc = make_float4(0.f, 0.f, 0.f, 0.f);
          for (int k = 0; k < 128; ++k) {
            float x = a1[k], y = a2[k];
            float4 w1 = *(const float4*)&p.Wc1[k * 128 + q];
            float4 w2 = *(const float4*)&p.Wc2[k * 128 + q];
            acc.x += x * w1.x + y * w2.x; acc.y += x * w1.y + y * w2.y;
            acc.z += x * w1.z + y * w2.z; acc.w += x * w1.w + y * w2.w;
          }
          if (side || ch != ct) {
            float* o = c_rep + (side ? ct : ch) * 128;
            o[q] = tanhf(acc.x); o[q + 1] = tanhf(acc.y);
            o[q + 2] = tanhf(acc.z); o[q + 3] = tanhf(acc.w);
          }
        }
        __syncthreads();
      }
    }
    grid_barrier();
  }
}

// ============================================================================
extern "C" void kernel_launch(void* const* d_in, const int* in_sizes, int n_in,
                              void* d_out, int out_size) {
  Params p;
  p.heads = (const int*)d_in[0];  p.tails = (const int*)d_in[1];
  p.times = (const float*)d_in[2];
  p.node_rep = (const float*)d_in[3];  p.cell_head = (const float*)d_in[4];
  p.hidden_head = (const float*)d_in[5]; p.cell_tail = (const float*)d_in[6];
  p.hidden_tail = (const float*)d_in[7];
  p.Weh1 = (const float*)d_in[8];  p.Weh2 = (const float*)d_in[9];  p.beh = (const float*)d_in[10];
  p.Wet1 = (const float*)d_in[11]; p.Wet2 = (const float*)d_in[12]; p.bet = (const float*)d_in[13];
  p.Wxh = (const float*)d_in[14];  p.Whh = (const float*)d_in[15];  p.bh = (const float*)d_in[16];
  p.Wdh = (const float*)d_in[17];  p.bdh = (const float*)d_in[18];
  p.Wxt = (const float*)d_in[19];  p.Wht = (const float*)d_in[20];  p.bt = (const float*)d_in[21];
  p.Wdt = (const float*)d_in[22];  p.bdt = (const float*)d_in[23];
  p.Wc1 = (const float*)d_in[24];  p.Wc2 = (const float*)d_in[25];
  p.out = (float*)d_out;
  p.S = in_sizes[0];

  static int configured = 0;
  if (!configured) {
    cudaFuncSetAttribute(main_kernel, cudaFuncAttributeMaxDynamicSharedMemorySize, SMEMF * 4);
    configured = 1;
  }
  scheduler_kernel<<<1, 1024>>>(p.heads, p.tails, p.S);
  main_kernel<<<NBLK, NTHR, SMEMF * 4>>>(p);
}

// round 11
// speedup vs baseline: 1.3475x; 1.3475x over previous
#include <cuda_runtime.h>
#include <math.h>
#include <stdint.h>

#define MAXS 2048
#define HSIZE 8192
#define HMASK 8191
#define NBLK 148
#define NTHR 256
#define SMEMB 172544
#define TILE_MIN 224

#define EPI_NONE 0
#define EPI_TANH 1
#define EPI_CADJ 2

typedef unsigned long long ull;

struct Params {
  const int *heads, *tails;
  const float *times;
  const float *node_rep, *cell_head, *hidden_head, *cell_tail, *hidden_tail;
  const float *Weh1, *Weh2, *beh, *Wet1, *Wet2, *bet;
  const float *Wxh, *Whh, *bh, *Wdh, *bdh;
  const float *Wxt, *Wht, *bt, *Wdt, *bdt;
  const float *Wc1, *Wc2;
  float *out;
  int S;
};

__device__ int g_cidH[MAXS], g_cidT[MAXS];
__device__ int g_slotNode[HSIZE];
__device__ int g_stepList[MAXS];
__device__ int g_waveOff[MAXS + 2];
__device__ int g_numWaves;

__device__ float c_rep[HSIZE * 128];
__device__ float c_ch [HSIZE * 128];
__device__ float c_hh [HSIZE * 128];
__device__ float c_ct [HSIZE * 128];
__device__ float c_ht [HSIZE * 128];
__device__ float c_rt [HSIZE];

__device__ unsigned g_barCnt;
__device__ volatile unsigned g_barGen;

__device__ __forceinline__ void grid_barrier() {
  __syncthreads();
  if (threadIdx.x == 0) {
    unsigned gen = g_barGen;
    __threadfence();
    if (atomicAdd(&g_barCnt, 1u) == gridDim.x - 1) {
      g_barCnt = 0; __threadfence(); g_barGen = gen + 1;
    } else {
      while (g_barGen == gen) { __nanosleep(32); }
    }
    __threadfence();
  }
  __syncthreads();
}

__device__ __forceinline__ float sigf(float x) { return 1.0f / (1.0f + expf(-x)); }
__device__ __forceinline__ void FFMA2(ull &d, ull a, ull b) {
  asm("fma.rn.f32x2 %0, %1, %2, %0;" : "+l"(d) : "l"(a), "l"(b));
}
__device__ __forceinline__ ull ADD2(ull a, ull b) {
  ull d; asm("add.rn.f32x2 %0, %1, %2;" : "=l"(d) : "l"(a), "l"(b)); return d;
}
__device__ __forceinline__ ull pack2(float a) {
  ull d; asm("mov.b64 %0, {%1, %1};" : "=l"(d) : "f"(a)); return d;
}
__device__ __forceinline__ void minit(uint32_t mb) {
  asm volatile("mbarrier.init.shared.b64 [%0], 1;" :: "r"(mb) : "memory");
}
__device__ __forceinline__ void etx(uint32_t mb, uint32_t bytes) {
  asm volatile("mbarrier.arrive.expect_tx.shared.b64 _, [%0], %1;" :: "r"(mb), "r"(bytes) : "memory");
}
__device__ __forceinline__ void bulkcp(uint32_t dst, const void* src, uint32_t bytes, uint32_t mb) {
  asm volatile("cp.async.bulk.shared::cta.global.mbarrier::complete_tx::bytes [%0], [%1], %2, [%3];"
               :: "r"(dst), "l"(src), "r"(bytes), "r"(mb) : "memory");
}
__device__ __forceinline__ void mwait(uint32_t mb, int ph) {
  asm volatile(
    "{\n\t.reg .pred P;\n\t"
    "W_%=: mbarrier.try_wait.parity.acquire.cta.shared::cta.b64 P, [%0], %1, 0x989680;\n\t"
    "@P bra D_%=;\n\t bra W_%=;\n\t D_%=:\n\t}"
    :: "r"(mb), "r"(ph) : "memory");
}

struct Pipe { uint32_t ws, mb; int ic, wc; float* wsp; };
__device__ __forceinline__ void pissue(Pipe& P, const float* s1, uint32_t bytes, const float* s2) {
  int b = P.ic & 1;
  if (threadIdx.x == 0) {
    etx(P.mb + 8 * b, s2 ? 2 * bytes : bytes);
    bulkcp(P.ws + b * 32768, s1, bytes, P.mb + 8 * b);
    if (s2) bulkcp(P.ws + b * 32768 + bytes, s2, bytes, P.mb + 8 * b);
  }
  P.ic++;
}
__device__ __forceinline__ const float* pwait(Pipe& P) {
  int b = P.wc & 1;
  mwait(P.mb + 8 * b, (P.wc >> 1) & 1);
  P.wc++;
  return P.wsp + b * 8192;
}

// ============================ scheduler =====================================
__global__ void __launch_bounds__(1024) scheduler_kernel(const int* heads, const int* tails, int S) {
  __shared__ int buf[HSIZE];
  __shared__ unsigned short sCH[MAXS], sCT[MAXS];
  __shared__ unsigned char asg[MAXS];
  __shared__ int sCnt, sBase, sW, sRemain;
  const int tid = threadIdx.x;
  for (int i = tid; i < HSIZE; i += 1024) { buf[i] = 0; g_slotNode[i] = -1; }
  for (int s = tid; s < S; s += 1024) asg[s] = 0;
  if (tid == 0) { sBase = 0; sW = 0; sRemain = S; }
  __syncthreads();
  for (int i = tid; i < 2 * S; i += 1024) {
    int step = i >> 1, isT = i & 1;
    int node = isT ? tails[step] : heads[step];
    int key = node + 1;
    unsigned slot = ((unsigned)node * 2654435761u) & HMASK;
    while (true) {
      int cur = buf[slot];
      if (cur == key) break;
      if (cur == 0) {
        int old = atomicCAS(&buf[slot], 0, key);
        if (old == 0) { g_slotNode[slot] = node; break; }
        if (old == key) break;
      }
      slot = (slot + 1u) & HMASK;
    }
    if (isT) { sCT[step] = (unsigned short)slot; g_cidT[step] = (int)slot; }
    else     { sCH[step] = (unsigned short)slot; g_cidH[step] = (int)slot; }
  }
  __syncthreads();
  while (sRemain > 0) {
    for (int s = tid; s < S; s += 1024)
      if (!asg[s]) { buf[sCH[s]] = 0x7FFFFFFF; buf[sCT[s]] = 0x7FFFFFFF; }
    __syncthreads();
    for (int s = tid; s < S; s += 1024)
      if (!asg[s]) { atomicMin(&buf[sCH[s]], 2 * s); atomicMin(&buf[sCT[s]], 2 * s + 1); }
    if (tid == 0) sCnt = 0;
    __syncthreads();
    for (int s = tid; s < S; s += 1024)
      if (!asg[s]) {
        int ch = sCH[s], ct = sCT[s];
        if (buf[ch] == 2 * s && (ct == ch || buf[ct] == 2 * s + 1)) {
          asg[s] = 1;
          g_stepList[sBase + atomicAdd(&sCnt, 1)] = s;
        }
      }
    __syncthreads();
    if (tid == 0) {
      g_waveOff[sW] = sBase; sBase += sCnt; sRemain -= sCnt; sW += 1; g_waveOff[sW] = sBase;
    }
    __syncthreads();
  }
  if (tid == 0) g_numWaves = sW;
}

// ================== merged edge GEMM: N=256 (E1|E2) ========================
__device__ void gemmEdge(Pipe& P, const Params& p, const float* X1, const float* X2,
                         float* E1, float* E2) {
  const int tid = threadIdx.x, w = tid >> 5, l = tid & 31;
  const int rg = (w & 3) << 2, half = w >> 2;
  ull acc[4][2];
#pragma unroll
  for (int r = 0; r < 4; ++r) { acc[r][0] = 0; acc[r][1] = 0; }
  pissue(P, p.Weh1, 16384, p.Wet1);
  for (int c = 0; c < 8; ++c) {
    if (c < 7) {
      const float* Wa = (c + 1 < 4) ? p.Weh1 : p.Weh2;
      const float* Wb = (c + 1 < 4) ? p.Wet1 : p.Wet2;
      int k0 = ((c + 1) & 3) * 32;
      pissue(P, Wa + k0 * 128, 16384, Wb + k0 * 128);
    }
    const float* Wc = pwait(P) + half * 4096;
    const float* A = (c < 4) ? X1 : X2;
    const int k0 = (c & 3) * 32;
#pragma unroll
    for (int kg = 0; kg < 8; ++kg) {
      float ab[4][4];
#pragma unroll
      for (int r = 0; r < 4; ++r)
        *(float4*)ab[r] = *(const float4*)&A[(rg + r) * 128 + k0 + kg * 4];
#pragma unroll
      for (int kk = 0; kk < 4; ++kk) {
        ulonglong2 wv = *(const ulonglong2*)&Wc[(kg * 4 + kk) * 128 + (l << 2)];
#pragma unroll
        for (int r = 0; r < 4; ++r) {
          ull av = pack2(ab[r][kk]);
          FFMA2(acc[r][0], av, wv.x); FFMA2(acc[r][1], av, wv.y);
        }
      }
    }
    __syncthreads();
  }
  const float* bias = half ? p.bet : p.beh;
  float* E = half ? E2 : E1;
  union U { ull u; float2 f; };
#pragma unroll
  for (int r = 0; r < 4; ++r) {
    U u0, u1; u0.u = acc[r][0]; u1.u = acc[r][1];
    float vals[4] = {u0.f.x, u0.f.y, u1.f.x, u1.f.y};
#pragma unroll
    for (int j = 0; j < 4; ++j) {
      int col = (l << 2) + j;
      E[(rg + r) * 128 + col] = tanhf(vals[j] + bias[col]);
    }
  }
  __syncthreads();
}

// ================== N=128 GEMM with k-split + reduction ====================
__device__ void gemm128(Pipe& P, const float* A1, const float* A2,
                        const float* W1, const float* W2, const float* bias,
                        int epi, const float* CAp, const float* dec,
                        float* outS, float* const* outG, float* red) {
  const int tid = threadIdx.x, w = tid >> 5, l = tid & 31;
  const int rg = (w & 3) << 2, ks = (w >> 2) << 4;
  const int nch = A2 ? 8 : 4;
  ull acc[4][2];
#pragma unroll
  for (int r = 0; r < 4; ++r) { acc[r][0] = 0; acc[r][1] = 0; }
  pissue(P, W1, 16384, 0);
  for (int c = 0; c < nch; ++c) {
    if (c + 1 < nch) {
      const float* W = (c + 1 < 4) ? W1 : W2;
      pissue(P, W + ((c + 1) & 3) * 32 * 128, 16384, 0);
    }
    const float* Wc = pwait(P);
    const float* A = (c < 4) ? A1 : A2;
    const int k0 = (c & 3) * 32 + ks;
#pragma unroll
    for (int kg = 0; kg < 4; ++kg) {
      float ab[4][4];
#pragma unroll
      for (int r = 0; r < 4; ++r)
        *(float4*)ab[r] = *(const float4*)&A[(rg + r) * 128 + k0 + kg * 4];
#pragma unroll
      for (int kk = 0; kk < 4; ++kk) {
        ulonglong2 wv = *(const ulonglong2*)&Wc[(ks + kg * 4 + kk) * 128 + (l << 2)];
#pragma unroll
        for (int r = 0; r < 4; ++r) {
          ull av = pack2(ab[r][kk]);
          FFMA2(acc[r][0], av, wv.x); FFMA2(acc[r][1], av, wv.y);
        }
      }
    }
    __syncthreads();
  }
  ull* rd = (ull*)red;
  if (w >= 4) {
    ull* dst = rd + (((w - 4) * 32 + l) << 3);
#pragma unroll
    for (int r = 0; r < 4; ++r) { dst[2 * r] = acc[r][0]; dst[2 * r + 1] = acc[r][1]; }
  }
  __syncthreads();
  if (w < 4) {
    const ull* src = rd + ((w * 32 + l) << 3);
    union U { ull u; float2 f; };
#pragma unroll
    for (int r = 0; r < 4; ++r) {
      acc[r][0] = ADD2(acc[r][0], src[2 * r]);
      acc[r][1] = ADD2(acc[r][1], src[2 * r + 1]);
      int row = rg + r;
      U u0, u1; u0.u = acc[r][0]; u1.u = acc[r][1];
      float vals[4] = {u0.f.x, u0.f.y, u1.f.x, u1.f.y};
      float* og = outG ? outG[row] : 0;
#pragma unroll
      for (int j = 0; j < 4; ++j) {
        int col = (l << 2) + j;
        float v = vals[j];
        if (bias) v += bias[col];
        if (epi == EPI_TANH) v = tanhf(v);
        else if (epi == EPI_CADJ) {
          float cs = tanhf(v);
          v = CAp[row * 128 + col] + cs * (dec[row] - 1.0f);
        }
        if (outS) outS[row * 128 + col] = v;
        else if (og) og[col] = v;
      }
    }
  }
  __syncthreads();
}

// ================== N=512 gates GEMM (full width, 16kk chunks) =============
__device__ void gemm512(Pipe& P, const float* A1, const float* A2,
                        const float* Wx, const float* Wh, const float* bias, float* Z) {
  const int tid = threadIdx.x, w = tid >> 5, l = tid & 31;
  const int rg = (w & 3) << 2, ch = w >> 2;
  ull acc[4][2][2];
#pragma unroll
  for (int r = 0; r < 4; ++r)
#pragma unroll
    for (int cs = 0; cs < 2; ++cs) { acc[r][cs][0] = 0; acc[r][cs][1] = 0; }
  pissue(P, Wx, 32768, 0);
  for (int c = 0; c < 16; ++c) {
    if (c < 15) {
      const float* W = (c + 1 < 8) ? Wx : Wh;
      pissue(P, W + ((c + 1) & 7) * 16 * 512, 32768, 0);
    }
    const float* Wc = pwait(P);
    const float* A = (c < 8) ? A1 : A2;
    const int k0 = (c & 7) * 16;
#pragma unroll
    for (int kg = 0; kg < 4; ++kg) {
      float ab[4][4];
#pragma unroll
      for (int r = 0; r < 4; ++r)
        *(float4*)ab[r] = *(const float4*)&A[(rg + r) * 128 + k0 + kg * 4];
#pragma unroll
      for (int kk = 0; kk < 4; ++kk) {
        const float* wb = &Wc[(kg * 4 + kk) * 512 + ch * 256 + (l << 2)];
        ulonglong2 wv0 = *(const ulonglong2*)wb;
        ulonglong2 wv1 = *(const ulonglong2*)(wb + 128);
#pragma unroll
        for (int r = 0; r < 4; ++r) {
          ull av = pack2(ab[r][kk]);
          FFMA2(acc[r][0][0], av, wv0.x); FFMA2(acc[r][0][1], av, wv0.y);
          FFMA2(acc[r][1][0], av, wv1.x); FFMA2(acc[r][1][1], av, wv1.y);
        }
      }
    }
    __syncthreads();
  }
  union U { ull u; float2 f; };
#pragma unroll
  for (int r = 0; r < 4; ++r)
#pragma unroll
    for (int cs = 0; cs < 2; ++cs) {
      U u0, u1; u0.u = acc[r][cs][0]; u1.u = acc[r][cs][1];
      float vals[4] = {u0.f.x, u0.f.y, u1.f.x, u1.f.y};
#pragma unroll
      for (int j = 0; j < 4; ++j) {
        int col = ch * 256 + cs * 128 + (l << 2) + j;
        Z[(rg + r) * 512 + col] = vals[j] + bias[col];
      }
    }
  __syncthreads();
}

// ============================== main kernel =================================
__global__ void __launch_bounds__(NTHR) main_kernel(Params p) {
  extern __shared__ float sm[];
  float *X1 = sm, *X2 = sm + 2048, *E1 = sm + 4096, *E2 = sm + 6144;
  float *H1 = sm + 8192, *H2 = sm + 10240, *S1 = sm + 12288, *S2 = sm + 14336;
  float *CAb = sm + 16384, *Z = sm + 18432, *WS = sm + 26624;
  float *misc = sm + 43008;
  uint64_t* mbar = (uint64_t*)misc;
  int *slotH = (int*)(misc + 4), *slotT = slotH + 16, *valid = slotT + 16;
  float *decH = (float*)(valid + 16), *decT = decH + 16;
  float **og = (float**)(decT + 16);

  const int tid = threadIdx.x;
  const int gsize = gridDim.x * blockDim.x;
  const int gtid = blockIdx.x * blockDim.x + tid;
  const int S = p.S;

  Pipe P;
  P.wsp = WS;
  P.ws = (uint32_t)__cvta_generic_to_shared(WS);
  P.mb = (uint32_t)__cvta_generic_to_shared(mbar);
  P.ic = 0; P.wc = 0;
  if (tid == 0) { minit(P.mb); minit(P.mb + 8); }
  __syncthreads();

  for (int e = gtid; e < HSIZE * 32; e += gsize) {
    int slot = e >> 5, q = (e & 31) << 2;
    int node = g_slotNode[slot];
    if (node < 0) continue;
    size_t src = (size_t)node * 128 + q;
    size_t dst = (size_t)slot * 128 + q;
    *(float4*)&c_rep[dst] = *(const float4*)&p.node_rep[src];
    *(float4*)&c_ch[dst]  = *(const float4*)&p.cell_head[src];
    *(float4*)&c_hh[dst]  = *(const float4*)&p.hidden_head[src];
    *(float4*)&c_ct[dst]  = *(const float4*)&p.cell_tail[src];
    *(float4*)&c_ht[dst]  = *(const float4*)&p.hidden_tail[src];
    if (q == 0) c_rt[slot] = 0.0f;
  }
  grid_barrier();

  const int nW = g_numWaves;
  for (int w = 0; w < nW; ++w) {
    const int s0 = g_waveOff[w];
    const int M = g_waveOff[w + 1] - s0;

    if (M >= TILE_MIN) {
      const int mT = (M + 15) >> 4;
      for (int job = blockIdx.x; job < mT; job += gridDim.x) {
        int m0 = job * 16;
        if (tid < 16) {
          int m = m0 + tid;
          int v = (m < M);
          int step = g_stepList[s0 + (v ? m : (M - 1))];
          int ch = g_cidH[step], ct = g_cidT[step];
          slotH[tid] = ch; slotT[tid] = ct; valid[tid] = v;
          float tm = p.times[step];
          decH[tid] = expf(-(tm - c_rt[ch]));
          decT[tid] = expf(-(tm - c_rt[ct]));
          if (v) { c_rt[ch] = tm; c_rt[ct] = tm; }
        }
        __syncthreads();
        for (int e = tid; e < 512; e += NTHR) {
          int r = e >> 5, q = (e & 31) << 2;
          int ch = slotH[r], ct = slotT[r];
          float4 rh = *(const float4*)&c_rep[ch * 128 + q];
          float4 rt = *(const float4*)&c_rep[ct * 128 + q];
          *(float4*)&X1[r * 128 + q] = rh;
          *(float4*)&X2[r * 128 + q] = rt;
          *(float4*)&H1[r * 128 + q] = *(const float4*)&c_hh[ch * 128 + q];
          *(float4*)&H2[r * 128 + q] = *(const float4*)&c_ht[ct * 128 + q];
          *(float4*)&S1[r * 128 + q] = *(const float4*)&c_ht[ch * 128 + q];
          *(float4*)&S2[r * 128 + q] = *(const float4*)&c_hh[ct * 128 + q];
          if (valid[r]) {
            int step = g_stepList[s0 + m0 + r];
            *(float4*)&p.out[(size_t)step * 128 + q] = rh;
            *(float4*)&p.out[(size_t)(S + step) * 128 + q] = rt;
          }
        }
        __syncthreads();

        gemmEdge(P, p, X1, X2, E1, E2);

        for (int e = tid; e < 512; e += NTHR) {
          int r = e >> 5, q = (e & 31) << 2;
          *(float4*)&CAb[r * 128 + q] = *(const float4*)&c_ch[slotH[r] * 128 + q];
        }
        __syncthreads();
        gemm128(P, CAb, 0, p.Wdh, 0, p.bdh, EPI_CADJ, CAb, decH, X1, 0, Z);
        for (int e = tid; e < 512; e += NTHR) {
          int r = e >> 5, q = (e & 31) << 2;
          *(float4*)&CAb[r * 128 + q] = *(const float4*)&c_ct[slotT[r] * 128 + q];
        }
        __syncthreads();
        gemm128(P, CAb, 0, p.Wdt, 0, p.bdt, EPI_CADJ, CAb, decT, X2, 0, Z);

        for (int side = 0; side < 2; ++side) {
          if (side == 0) gemm512(P, E1, H1, p.Wxh, p.Whh, p.bh, Z);
          else           gemm512(P, E2, H2, p.Wxt, p.Wht, p.bt, Z);
          float* Xc = side ? X2 : X1;
          float* cel = side ? c_ct : c_ch;
          float* hid = side ? c_ht : c_hh;
          int* slot = side ? slotT : slotH;
          for (int e = tid; e < 2048; e += NTHR) {
            int r = e >> 7, c = e & 127;
            if (!valid[r]) continue;
            const float* z = &Z[r * 512];
            float ii = sigf(z[c]), ff = sigf(z[128 + c]);
            float oo = sigf(z[256 + c]), gg = tanhf(z[384 + c]);
            float cn = ff * Xc[r * 128 + c] + ii * gg;
            float hn = oo * tanhf(cn);
            Xc[r * 128 + c] = hn;
            cel[slot[r] * 128 + c] = cn;
            hid[slot[r] * 128 + c] = hn;
          }
          __syncthreads();
        }

        if (tid < 16)
          og[tid] = (valid[tid] && slotH[tid] != slotT[tid]) ? (c_rep + slotH[tid] * 128) : 0;
        __syncthreads();
        gemm128(P, X1, S1, p.Wc1, p.Wc2, 0, EPI_TANH, 0, 0, 0, og, Z);
        if (tid < 16) og[tid] = valid[tid] ? (c_rep + slotT[tid] * 128) : 0;
        __syncthreads();
        gemm128(P, S2, X2, p.Wc1, p.Wc2, 0, EPI_TANH, 0, 0, 0, og, Z);
      }
    } else {
      // ================= GEMV path: one step per block-job ==================
      float *aRH = sm, *aRT = sm + 128, *aHH = sm + 256, *aHT = sm + 384;
      float *aTh = sm + 512, *aHt = sm + 640, *aCH = sm + 768, *aCT = sm + 896;
      float *eH = sm + 1024, *eT = sm + 1152, *cjH = sm + 1280, *cjT = sm + 1408;
      float *hnH = sm + 1536, *hnT = sm + 1664;
      float *zz = sm + 1792;
      float *dc = sm + 2816;
      for (int job = blockIdx.x; job < M; job += gridDim.x) {
        int step = g_stepList[s0 + job];
        int ch = g_cidH[step], ct = g_cidT[step];
        if (tid == 0) {
          float tm = p.times[step];
          dc[0] = expf(-(tm - c_rt[ch]));
          dc[1] = expf(-(tm - c_rt[ct]));
          c_rt[ch] = tm; c_rt[ct] = tm;
        }
        if (tid < 128) {
          int t = tid;
          float rh = c_rep[ch * 128 + t], rt = c_rep[ct * 128 + t];
          aRH[t] = rh; aRT[t] = rt;
          aHH[t] = c_hh[ch * 128 + t]; aHT[t] = c_ht[ct * 128 + t];
          aTh[t] = c_ht[ch * 128 + t]; aHt[t] = c_hh[ct * 128 + t];
          aCH[t] = c_ch[ch * 128 + t]; aCT[t] = c_ct[ct * 128 + t];
          p.out[(size_t)step * 128 + t] = rh;
          p.out[(size_t)(S + step) * 128 + t] = rt;
        }
        __syncthreads();
        if (tid < 64) {
          int side = tid >> 5, q = (tid & 31) << 2;
          const float *W1 = side ? p.Wet1 : p.Weh1, *W2 = side ? p.Wet2 : p.Weh2;
          const float *bb = side ? p.bet : p.beh;
          float4 acc = *(const float4*)&bb[q];
          for (int k = 0; k < 128; ++k) {
            float a0 = aRH[k], a1 = aRT[k];
            float4 w1 = *(const float4*)&W1[k * 128 + q];
            float4 w2 = *(const float4*)&W2[k * 128 + q];
            acc.x += a0 * w1.x + a1 * w2.x; acc.y += a0 * w1.y + a1 * w2.y;
            acc.z += a0 * w1.z + a1 * w2.z; acc.w += a0 * w1.w + a1 * w2.w;
          }
          float* e = side ? eT : eH;
          e[q] = tanhf(acc.x); e[q + 1] = tanhf(acc.y);
          e[q + 2] = tanhf(acc.z); e[q + 3] = tanhf(acc.w);
        } else if (tid < 128) {
          int side = (tid >> 5) & 1, q = (tid & 31) << 2;
          const float* Wd = side ? p.Wdt : p.Wdh;
          const float* bd = side ? p.bdt : p.bdh;
          const float* cc = side ? aCT : aCH;
          float d = dc[side];
          float4 acc = *(const float4*)&bd[q];
          for (int k = 0; k < 128; ++k) {
            float a0 = cc[k];
            float4 wv = *(const float4*)&Wd[k * 128 + q];
            acc.x += a0 * wv.x; acc.y += a0 * wv.y; acc.z += a0 * wv.z; acc.w += a0 * wv.w;
          }
          float* cj = side ? cjT : cjH;
          cj[q] = cc[q] + tanhf(acc.x) * (d - 1.f);
          cj[q + 1] = cc[q + 1] + tanhf(acc.y) * (d - 1.f);
          cj[q + 2] = cc[q + 2] + tanhf(acc.z) * (d - 1.f);
          cj[q + 3] = cc[q + 3] + tanhf(acc.w) * (d - 1.f);
        }
        __syncthreads();
        {
          int side = tid >> 7, gate = (tid >> 5) & 3, q = (tid & 31) << 2;
          int col = gate * 128 + q;
          const float* Wx = side ? p.Wxt : p.Wxh;
          const float* Wh = side ? p.Wht : p.Whh;
          const float* bb = side ? p.bt : p.bh;
          const float* e = side ? eT : eH;
          const float* hh = side ? aHT : aHH;
          float4 acc = *(const float4*)&bb[col];
          for (int k = 0; k < 128; ++k) {
            float x = e[k], h = hh[k];
            float4 w1 = *(const float4*)&Wx[k * 512 + col];
            float4 w2 = *(const float4*)&Wh[k * 512 + col];
            acc.x += x * w1.x + h * w2.x; acc.y += x * w1.y + h * w2.y;
            acc.z += x * w1.z + h * w2.z; acc.w += x * w1.w + h * w2.w;
          }
          *(float4*)&zz[side * 512 + col] = acc;
        }
        __syncthreads();
        {
          int side = tid >> 7, c = tid & 127;
          const float* z = zz + side * 512;
          float ii = sigf(z[c]), ff = sigf(z[128 + c]), oo = sigf(z[256 + c]), gg = tanhf(z[384 + c]);
          float cn = ff * (side ? cjT[c] : cjH[c]) + ii * gg;
          float hn = oo * tanhf(cn);
          if (side) { hnT[c] = hn; c_ct[ct * 128 + c] = cn; c_ht[ct * 128 + c] = hn; }
          else      { hnH[c] = hn; c_ch[ch * 128 + c] = cn; c_hh[ch * 128 + c] = hn; }
        }
        __syncthreads();
        if (tid < 64) {
          int side = tid >> 5, q = (tid & 31) << 2;
          const float* a1 = side ? aHt : hnH;
          const float* a2 = side ? hnT : aTh;
          float4 acc = make_float4(0.f, 0.f, 0.f, 0.f);
          for (int k = 0; k < 128; ++k) {
            float x = a1[k], y = a2[k];
            float4 w1 = *(const float4*)&p.Wc1[k * 128 + q];
            float4 w2 = *(const float4*)&p.Wc2[k * 128 + q];
            acc.x += x * w1.x + y * w2.x; acc.y += x * w1.y + y * w2.y;
            acc.z += x * w1.z + y * w2.z; acc.w += x * w1.w + y * w2.w;
          }
          if (side || ch != ct) {
            float* o = c_rep + (side ? ct : ch) * 128;
            o[q] = tanhf(acc.x); o[q + 1] = tanhf(acc.y);
            o[q + 2] = tanhf(acc.z); o[q + 3] = tanhf(acc.w);
          }
        }
        __syncthreads();
      }
    }
    grid_barrier();
  }
}

// ============================================================================
extern "C" void kernel_launch(void* const* d_in, const int* in_sizes, int n_in,
                              void* d_out, int out_size) {
  Params p;
  p.heads = (const int*)d_in[0];  p.tails = (const int*)d_in[1];
  p.times = (const float*)d_in[2];
  p.node_rep = (const float*)d_in[3];  p.cell_head = (const float*)d_in[4];
  p.hidden_head = (const float*)d_in[5]; p.cell_tail = (const float*)d_in[6];
  p.hidden_tail = (const float*)d_in[7];
  p.Weh1 = (const float*)d_in[8];  p.Weh2 = (const float*)d_in[9];  p.beh = (const float*)d_in[10];
  p.Wet1 = (const float*)d_in[11]; p.Wet2 = (const float*)d_in[12]; p.bet = (const float*)d_in[13];
  p.Wxh = (const float*)d_in[14];  p.Whh = (const float*)d_in[15];  p.bh = (const float*)d_in[16];
  p.Wdh = (const float*)d_in[17];  p.bdh = (const float*)d_in[18];
  p.Wxt = (const float*)d_in[19];  p.Wht = (const float*)d_in[20];  p.bt = (const float*)d_in[21];
  p.Wdt = (const float*)d_in[22];  p.bdt = (const float*)d_in[23];
  p.Wc1 = (const float*)d_in[24];  p.Wc2 = (const float*)d_in[25];
  p.out = (float*)d_out;
  p.S = in_sizes[0];

  cudaFuncSetAttribute(main_kernel, cudaFuncAttributeMaxDynamicSharedMemorySize, SMEMB);
  scheduler_kernel<<<1, 1024>>>(p.heads, p.tails, p.S);
  main_kernel<<<NBLK, NTHR, SMEMB>>>(p);
}